// round 14
// baseline (speedup 1.0000x reference)
#include <cuda_runtime.h>
#include <cuda_fp16.h>
#include <stdint.h>
#include <math.h>

#define N_TOK 8192
#define C_DIM 1024
#define H_DIM 4096
#define E_NUM 5
#define PADDED_CAP (N_TOK + E_NUM * 128)   // 8832

// ---------------------------------------------------------------------------
// Device scratch (allocation-free per harness rules)
// NOTE: activations in device globals are fine (R5-R13, incl. cp.async);
// staging WEIGHTS in device globals is a proven 8-11x regression (R6/R8) —
// weights are cp.async'd straight from the harness input pointers here.
// ---------------------------------------------------------------------------
__device__ float g_scale[N_TOK];
__device__ int   g_sorted[N_TOK];
__device__ int   g_count[E_NUM];
__device__ int   g_offset[E_NUM + 1];
__device__ int   g_poff[E_NUM + 1];
__device__ int   g_cursor[E_NUM];

__device__ __align__(16) __half g_h_f16[(size_t)N_TOK * C_DIM];        // layernormed tokens
__device__ __align__(16) __half g_act_f16[(size_t)PADDED_CAP * H_DIM]; // relu^2 activations

// ---------------------------------------------------------------------------
// PTX helpers
// ---------------------------------------------------------------------------
__device__ __forceinline__ uint32_t smem_u32(const void* p) {
    uint32_t a;
    asm("{ .reg .u64 t; cvta.to.shared.u64 t, %1; cvt.u32.u64 %0, t; }" : "=r"(a) : "l"(p));
    return a;
}
__device__ __forceinline__ uint32_t lds32(uint32_t a) {
    uint32_t v;
    asm volatile("ld.shared.b32 %0, [%1];" : "=r"(v) : "r"(a));
    return v;
}
__device__ __forceinline__ void cp16(uint32_t dst, const void* src) {
    asm volatile("cp.async.cg.shared.global [%0], [%1], 16;" :: "r"(dst), "l"(src));
}
__device__ __forceinline__ void cp16s(uint32_t dst, const void* src, uint32_t sz) {
    asm volatile("cp.async.cg.shared.global [%0], [%1], 16, %2;" :: "r"(dst), "l"(src), "r"(sz));
}
__device__ __forceinline__ void cp_commit() {
    asm volatile("cp.async.commit_group;" ::: "memory");
}
__device__ __forceinline__ void cp_wait1() {
    asm volatile("cp.async.wait_group 1;" ::: "memory");
}
__device__ __forceinline__ void cp_wait0() {
    asm volatile("cp.async.wait_group 0;" ::: "memory");
}
__device__ __forceinline__ void mma16816(float* c, const uint32_t* a, uint32_t b0, uint32_t b1) {
    asm volatile("mma.sync.aligned.m16n8k16.row.col.f32.f16.f16.f32 "
                 "{%0,%1,%2,%3}, {%4,%5,%6,%7}, {%8,%9}, {%0,%1,%2,%3};"
                 : "+f"(c[0]), "+f"(c[1]), "+f"(c[2]), "+f"(c[3])
                 : "r"(a[0]), "r"(a[1]), "r"(a[2]), "r"(a[3]), "r"(b0), "r"(b1));
}
__device__ __forceinline__ uint32_t pack_f16(float x, float y) {
    __half2 h = __floats2half2_rn(x, y);
    return *reinterpret_cast<uint32_t*>(&h);
}

// ---------------------------------------------------------------------------
// Small pipeline kernels (validated)
// ---------------------------------------------------------------------------
__global__ void __launch_bounds__(256) ln_conf_kernel(
    const float* __restrict__ x, const int* __restrict__ winners,
    const float* __restrict__ gamma, const float* __restrict__ beta,
    const float* __restrict__ wc, const float* __restrict__ bc)
{
    int n = blockIdx.x, tid = threadIdx.x;
    const float* xr = x + (size_t)n * C_DIM;
    float xv[4], s = 0.f, s2 = 0.f;
#pragma unroll
    for (int i = 0; i < 4; i++) { float v = xr[tid + 256 * i]; xv[i] = v; s += v; s2 += v * v; }
#pragma unroll
    for (int off = 16; off > 0; off >>= 1) {
        s  += __shfl_down_sync(0xffffffffu, s,  off);
        s2 += __shfl_down_sync(0xffffffffu, s2, off);
    }
    __shared__ float sh1[8], sh2[8];
    __shared__ float s_mean, s_rstd;
    int warp = tid >> 5, lane = tid & 31;
    if (lane == 0) { sh1[warp] = s; sh2[warp] = s2; }
    __syncthreads();
    if (tid == 0) {
        float ts = 0.f, ts2 = 0.f;
#pragma unroll
        for (int w = 0; w < 8; w++) { ts += sh1[w]; ts2 += sh2[w]; }
        float mean = ts * (1.f / C_DIM);
        float var = ts2 * (1.f / C_DIM) - mean * mean;
        s_mean = mean; s_rstd = rsqrtf(var + 1e-5f);
    }
    __syncthreads();
    float mean = s_mean, rstd = s_rstd;
    int win = winners[n];
    const float* wcr = wc + (size_t)win * C_DIM;
    float dot = 0.f;
#pragma unroll
    for (int i = 0; i < 4; i++) {
        int c = tid + 256 * i;
        float hv = (xv[i] - mean) * rstd * gamma[c] + beta[c];
        g_h_f16[(size_t)n * C_DIM + c] = __float2half_rn(hv);
        dot += hv * wcr[c];
    }
#pragma unroll
    for (int off = 16; off > 0; off >>= 1) dot += __shfl_down_sync(0xffffffffu, dot, off);
    if (lane == 0) sh1[warp] = dot;
    __syncthreads();
    if (tid == 0) {
        float t = 0.f;
#pragma unroll
        for (int w = 0; w < 8; w++) t += sh1[w];
        t += bc[win];
        float conf = 1.f / (1.f + expf(-t));
        g_scale[n] = conf / (conf + 1e-6f);
        atomicAdd(&g_count[win], 1);
    }
}

__global__ void scan_kernel() {
    if (threadIdx.x == 0) {
        int acc = 0, pacc = 0;
        g_offset[0] = 0; g_poff[0] = 0;
        for (int e = 0; e < E_NUM; e++) {
            int c = g_count[e];
            acc += c;
            g_offset[e + 1] = acc;
            g_cursor[e] = g_offset[e];
            pacc += ((c + 127) / 128) * 128;
            g_poff[e + 1] = pacc;
        }
    }
}

__global__ void scatter_kernel(const int* __restrict__ winners) {
    int n = blockIdx.x * blockDim.x + threadIdx.x;
    if (n < N_TOK) {
        int e = winners[n];
        int pos = atomicAdd(&g_cursor[e], 1);
        g_sorted[pos] = n;
    }
}

// ---------------------------------------------------------------------------
// HMMA GEMM, pure fp16 math, CTA 128x128, BK=32, 8 warps (2M x 4N),
// warp tile 64x32, 2 CTAs/SM, 3-stage full-cp.async pipeline.
// A: cp.async fp16 from g_h_f16 (gathered) / g_act_f16 into swizzled smem.
//    A smem: [m 128][k 32] fp16, 64B rows, XOR group swizzle
//    phys(m, kp) = m*64 + (((kp>>2) ^ ((m>>1)&3))<<4) + ((kp&3)<<2)
// B: cp.async RAW fp32 straight from harness w pointer, [k 32][n 128],
//    row stride 528B (conflict-free for the 4-LDS frag pattern), converted
//    to fp16 pairs during fragment load (cvt is free: ALU was at 13%).
// The inter-chunk gap contains ONLY wait_group + barrier.
// ---------------------------------------------------------------------------
#define BK 32
#define ST_B    8192
#define B_ROWB  528
#define STAGE   25088          // 8192 + 32*528

template<bool G1>
__global__ void __launch_bounds__(256, 2) gemm_mma(
    const float* __restrict__ w,      // G1: w1 [E][C][H]; G2: w2 [E][H][C]
    const float* __restrict__ x,
    float* __restrict__ out)
{
    constexpr int K  = G1 ? C_DIM : H_DIM;   // reduction dim
    constexpr int NB = G1 ? H_DIM : C_DIM;   // output-feature dim
    constexpr int NC = K / BK;

    int e     = blockIdx.z;
    int pbase = g_poff[e];
    int pcnt  = g_poff[e + 1] - pbase;
    int row0  = blockIdx.y * 128;
    if (row0 >= pcnt) return;
    int coln0 = blockIdx.x * 128;
    int prow0 = pbase + row0;

    extern __shared__ __align__(16) char sm[];
    uint32_t sb = smem_u32(sm);

    int tid = threadIdx.x, lane = tid & 31, wid = tid >> 5;
    int wm = wid & 1, wn = wid >> 1;
    int g4 = lane >> 2, t4 = lane & 3;

    int obase = g_offset[e];
    int cnt   = g_offset[e + 1] - obase;

    // ---- A cp.async sources: 2 rows per thread, one 16B chunk each ----
    int kq = tid & 3;                         // 16B chunk within 64B row-chunk
    const __half* asrc[2];
    uint32_t asz[2], adst[2];
#pragma unroll
    for (int p = 0; p < 2; p++) {
        int m = p * 64 + (tid >> 2);
        adst[p] = (uint32_t)(m * 64 + ((kq ^ ((m >> 1) & 3)) << 4));
        if (G1) {
            int gr = row0 + m;
            if (gr < cnt) {
                asrc[p] = g_h_f16 + (size_t)g_sorted[obase + gr] * C_DIM + kq * 8;
                asz[p] = 16;
            } else { asrc[p] = g_h_f16; asz[p] = 0; }
        } else {
            asrc[p] = g_act_f16 + (size_t)(prow0 + m) * H_DIM + kq * 8;
            asz[p] = 16;
        }
    }
    // ---- B cp.async sources: 4 16B chunks per thread (raw fp32 rows) ----
    // chunk idx = q*256 + tid: row r = idx>>5 (0..31), col chunk ch = idx&31
    const float* bsrc[4];
    uint32_t bdst[4];
#pragma unroll
    for (int q = 0; q < 4; q++) {
        int idx = q * 256 + tid;
        int r = idx >> 5, ch = idx & 31;
        bsrc[q] = w + (size_t)e * C_DIM * H_DIM + (size_t)r * NB + coln0 + ch * 4;
        bdst[q] = (uint32_t)(ST_B + r * B_ROWB + ch * 16);
    }

    float acc[4][4][4];
#pragma unroll
    for (int i = 0; i < 4; i++)
#pragma unroll
        for (int j = 0; j < 4; j++)
#pragma unroll
            for (int q = 0; q < 4; q++) acc[i][j][q] = 0.f;

    auto issue = [&](int c) {
        uint32_t st = sb + (uint32_t)(c % 3) * STAGE;
        int ko = c * BK;
#pragma unroll
        for (int p = 0; p < 2; p++)
            cp16s(st + adst[p], asrc[p] + ko, asz[p]);
#pragma unroll
        for (int q = 0; q < 4; q++)
            cp16(st + bdst[q], bsrc[q] + (size_t)ko * NB);
        cp_commit();
    };

    issue(0);
    if (NC > 1) issue(1);

#pragma unroll 1
    for (int c = 0; c < NC; c++) {
        if (c + 1 < NC) cp_wait1(); else cp_wait0();
        __syncthreads();
        // stage (c+2)%3 == (c-1)%3: its readers finished before the barrier
        if (c + 2 < NC) issue(c + 2);

        uint32_t st = sb + (uint32_t)(c % 3) * STAGE;
#pragma unroll
        for (int ks = 0; ks < 2; ks++) {
            uint32_t af[4][4];
#pragma unroll
            for (int mi = 0; mi < 4; mi++) {
                int m = wm * 64 + mi * 16 + g4;
                int s = (m >> 1) & 3;
                uint32_t r0 = st + (uint32_t)(m * 64 + (((ks * 2)     ^ s) << 4) + (t4 << 2));
                uint32_t r2 = st + (uint32_t)(m * 64 + (((ks * 2 + 1) ^ s) << 4) + (t4 << 2));
                af[mi][0] = lds32(r0);
                af[mi][1] = lds32(r0 + 512);   // row m+8, same swizzle key
                af[mi][2] = lds32(r2);
                af[mi][3] = lds32(r2 + 512);
            }
            uint32_t bf[4][2];
#pragma unroll
            for (int nt = 0; nt < 4; nt++) {
                // raw fp32: rows k = ks*16 + 2*t4 (+1), and +8 pair
                uint32_t bb = st + (uint32_t)(ST_B + (ks * 16 + 2 * t4) * B_ROWB
                                              + (wn * 32 + nt * 8 + g4) * 4);
                float f0 = __uint_as_float(lds32(bb));
                float f1 = __uint_as_float(lds32(bb + B_ROWB));
                float f2 = __uint_as_float(lds32(bb + 8 * B_ROWB));
                float f3 = __uint_as_float(lds32(bb + 9 * B_ROWB));
                bf[nt][0] = pack_f16(f0, f1);
                bf[nt][1] = pack_f16(f2, f3);
            }
#pragma unroll
            for (int mi = 0; mi < 4; mi++)
#pragma unroll
                for (int nt = 0; nt < 4; nt++)
                    mma16816(acc[mi][nt], af[mi], bf[nt][0], bf[nt][1]);
        }
    }

    // ---- epilogue (unchanged from R12) ----
    if (G1) {
#pragma unroll
        for (int mi = 0; mi < 4; mi++) {
            int gr = wm * 64 + mi * 16 + g4;
            size_t r0g = (size_t)(prow0 + gr)     * H_DIM;
            size_t r1g = (size_t)(prow0 + gr + 8) * H_DIM;
#pragma unroll
            for (int nt = 0; nt < 4; nt++) {
                int gc = coln0 + wn * 32 + nt * 8 + t4 * 2;
                float* cc = acc[mi][nt];
                float v0x = fmaxf(cc[0], 0.f); v0x *= v0x;
                float v0y = fmaxf(cc[1], 0.f); v0y *= v0y;
                float v1x = fmaxf(cc[2], 0.f); v1x *= v1x;
                float v1y = fmaxf(cc[3], 0.f); v1y *= v1y;
                *reinterpret_cast<uint32_t*>(g_act_f16 + r0g + gc) = pack_f16(v0x, v0y);
                *reinterpret_cast<uint32_t*>(g_act_f16 + r1g + gc) = pack_f16(v1x, v1y);
            }
        }
    } else {
#pragma unroll
        for (int mi = 0; mi < 4; mi++) {
            int rl0 = row0 + wm * 64 + mi * 16 + g4;
            int tok0 = -1, tok1 = -1;
            float sc0 = 0.f, sc1 = 0.f;
            if (rl0 < cnt)     { tok0 = g_sorted[obase + rl0];     sc0 = g_scale[tok0]; }
            if (rl0 + 8 < cnt) { tok1 = g_sorted[obase + rl0 + 8]; sc1 = g_scale[tok1]; }
#pragma unroll
            for (int nt = 0; nt < 4; nt++) {
                int gc = coln0 + wn * 32 + nt * 8 + t4 * 2;
                float* cc = acc[mi][nt];
                if (tok0 >= 0) {
                    size_t o = (size_t)tok0 * C_DIM + gc;
                    float2 xv = *reinterpret_cast<const float2*>(x + o);
                    float2 ov; ov.x = xv.x + cc[0] * sc0; ov.y = xv.y + cc[1] * sc0;
                    *reinterpret_cast<float2*>(out + o) = ov;
                }
                if (tok1 >= 0) {
                    size_t o = (size_t)tok1 * C_DIM + gc;
                    float2 xv = *reinterpret_cast<const float2*>(x + o);
                    float2 ov; ov.x = xv.x + cc[2] * sc1; ov.y = xv.y + cc[3] * sc1;
                    *reinterpret_cast<float2*>(out + o) = ov;
                }
            }
        }
    }
}

// ---------------------------------------------------------------------------
extern "C" void kernel_launch(void* const* d_in, const int* in_sizes, int n_in,
                              void* d_out, int out_size)
{
    const float* x       = (const float*)d_in[0];
    const int*   winners = (const int*)  d_in[1];
    const float* gamma   = (const float*)d_in[2];
    const float* beta    = (const float*)d_in[3];
    const float* w1      = (const float*)d_in[4];
    const float* w2      = (const float*)d_in[5];
    const float* wc      = (const float*)d_in[6];
    const float* bc      = (const float*)d_in[7];
    float* out = (float*)d_out;

    const int SMEM = 3 * STAGE;   // 75264 B dynamic
    cudaFuncSetAttribute(gemm_mma<true>,  cudaFuncAttributeMaxDynamicSharedMemorySize, SMEM);
    cudaFuncSetAttribute(gemm_mma<false>, cudaFuncAttributeMaxDynamicSharedMemorySize, SMEM);

    // zero per-expert counters via memset nodes (graph-capturable, no alloc)
    void* p_count = 0;
    void* p_cursor = 0;
    cudaGetSymbolAddress(&p_count,  g_count);
    cudaGetSymbolAddress(&p_cursor, g_cursor);
    cudaMemsetAsync(p_count,  0, E_NUM * sizeof(int));
    cudaMemsetAsync(p_cursor, 0, E_NUM * sizeof(int));

    ln_conf_kernel<<<N_TOK, 256>>>(x, winners, gamma, beta, wc, bc);
    scan_kernel<<<1, 32>>>();
    scatter_kernel<<<N_TOK / 256, 256>>>(winners);

    gemm_mma<true><<<dim3(H_DIM / 128, PADDED_CAP / 128, E_NUM), 256, SMEM>>>(w1, x, out);
    gemm_mma<false><<<dim3(C_DIM / 128, PADDED_CAP / 128, E_NUM), 256, SMEM>>>(w2, x, out);
}

// round 15
// speedup vs baseline: 1.0868x; 1.0868x over previous
#include <cuda_runtime.h>
#include <cuda_fp16.h>
#include <stdint.h>
#include <math.h>

#define N_TOK 8192
#define C_DIM 1024
#define H_DIM 4096
#define E_NUM 5
#define PADDED_CAP (N_TOK + E_NUM * 128)   // 8832

// ---------------------------------------------------------------------------
// Device scratch (allocation-free per harness rules)
// NOTE: activations in device globals are fine (R5-R14, incl. cp.async);
// staging WEIGHTS in device globals is a proven 8-11x regression (R6/R8) —
// weights are always read straight from the harness input pointers.
// ---------------------------------------------------------------------------
__device__ float g_scale[N_TOK];
__device__ int   g_sorted[N_TOK];
__device__ int   g_count[E_NUM];
__device__ int   g_offset[E_NUM + 1];
__device__ int   g_poff[E_NUM + 1];
__device__ int   g_cursor[E_NUM];

__device__ __align__(16) __half g_h_f16[(size_t)N_TOK * C_DIM];        // layernormed tokens
__device__ __align__(16) __half g_act_f16[(size_t)PADDED_CAP * H_DIM]; // relu^2 activations

// ---------------------------------------------------------------------------
// PTX helpers
// ---------------------------------------------------------------------------
__device__ __forceinline__ uint32_t smem_u32(const void* p) {
    uint32_t a;
    asm("{ .reg .u64 t; cvta.to.shared.u64 t, %1; cvt.u32.u64 %0, t; }" : "=r"(a) : "l"(p));
    return a;
}
__device__ __forceinline__ uint32_t lds32(uint32_t a) {
    uint32_t v;
    asm volatile("ld.shared.b32 %0, [%1];" : "=r"(v) : "r"(a));
    return v;
}
__device__ __forceinline__ void cp16s(uint32_t dst, const void* src, uint32_t sz) {
    asm volatile("cp.async.cg.shared.global [%0], [%1], 16, %2;" :: "r"(dst), "l"(src), "r"(sz));
}
__device__ __forceinline__ void cp_commit() {
    asm volatile("cp.async.commit_group;" ::: "memory");
}
__device__ __forceinline__ void cp_wait0() {
    asm volatile("cp.async.wait_group 0;" ::: "memory");
}
__device__ __forceinline__ void mma16816(float* c, const uint32_t* a, uint32_t b0, uint32_t b1) {
    asm volatile("mma.sync.aligned.m16n8k16.row.col.f32.f16.f16.f32 "
                 "{%0,%1,%2,%3}, {%4,%5,%6,%7}, {%8,%9}, {%0,%1,%2,%3};"
                 : "+f"(c[0]), "+f"(c[1]), "+f"(c[2]), "+f"(c[3])
                 : "r"(a[0]), "r"(a[1]), "r"(a[2]), "r"(a[3]), "r"(b0), "r"(b1));
}
__device__ __forceinline__ uint32_t pack_f16(float x, float y) {
    __half2 h = __floats2half2_rn(x, y);
    return *reinterpret_cast<uint32_t*>(&h);
}

// ---------------------------------------------------------------------------
// Small pipeline kernels (validated)
// ---------------------------------------------------------------------------
__global__ void __launch_bounds__(256) ln_conf_kernel(
    const float* __restrict__ x, const int* __restrict__ winners,
    const float* __restrict__ gamma, const float* __restrict__ beta,
    const float* __restrict__ wc, const float* __restrict__ bc)
{
    int n = blockIdx.x, tid = threadIdx.x;
    const float* xr = x + (size_t)n * C_DIM;
    float xv[4], s = 0.f, s2 = 0.f;
#pragma unroll
    for (int i = 0; i < 4; i++) { float v = xr[tid + 256 * i]; xv[i] = v; s += v; s2 += v * v; }
#pragma unroll
    for (int off = 16; off > 0; off >>= 1) {
        s  += __shfl_down_sync(0xffffffffu, s,  off);
        s2 += __shfl_down_sync(0xffffffffu, s2, off);
    }
    __shared__ float sh1[8], sh2[8];
    __shared__ float s_mean, s_rstd;
    int warp = tid >> 5, lane = tid & 31;
    if (lane == 0) { sh1[warp] = s; sh2[warp] = s2; }
    __syncthreads();
    if (tid == 0) {
        float ts = 0.f, ts2 = 0.f;
#pragma unroll
        for (int w = 0; w < 8; w++) { ts += sh1[w]; ts2 += sh2[w]; }
        float mean = ts * (1.f / C_DIM);
        float var = ts2 * (1.f / C_DIM) - mean * mean;
        s_mean = mean; s_rstd = rsqrtf(var + 1e-5f);
    }
    __syncthreads();
    float mean = s_mean, rstd = s_rstd;
    int win = winners[n];
    const float* wcr = wc + (size_t)win * C_DIM;
    float dot = 0.f;
#pragma unroll
    for (int i = 0; i < 4; i++) {
        int c = tid + 256 * i;
        float hv = (xv[i] - mean) * rstd * gamma[c] + beta[c];
        g_h_f16[(size_t)n * C_DIM + c] = __float2half_rn(hv);
        dot += hv * wcr[c];
    }
#pragma unroll
    for (int off = 16; off > 0; off >>= 1) dot += __shfl_down_sync(0xffffffffu, dot, off);
    if (lane == 0) sh1[warp] = dot;
    __syncthreads();
    if (tid == 0) {
        float t = 0.f;
#pragma unroll
        for (int w = 0; w < 8; w++) t += sh1[w];
        t += bc[win];
        float conf = 1.f / (1.f + expf(-t));
        g_scale[n] = conf / (conf + 1e-6f);
        atomicAdd(&g_count[win], 1);
    }
}

__global__ void scan_kernel() {
    if (threadIdx.x == 0) {
        int acc = 0, pacc = 0;
        g_offset[0] = 0; g_poff[0] = 0;
        for (int e = 0; e < E_NUM; e++) {
            int c = g_count[e];
            acc += c;
            g_offset[e + 1] = acc;
            g_cursor[e] = g_offset[e];
            pacc += ((c + 127) / 128) * 128;
            g_poff[e + 1] = pacc;
        }
    }
}

__global__ void scatter_kernel(const int* __restrict__ winners) {
    int n = blockIdx.x * blockDim.x + threadIdx.x;
    if (n < N_TOK) {
        int e = winners[n];
        int pos = atomicAdd(&g_cursor[e], 1);
        g_sorted[pos] = n;
    }
}

// ---------------------------------------------------------------------------
// HMMA GEMM, pure fp16 (1 MMA product per tile), CTA 128x128, BK=32,
// 8 warps (2M x 4N), warp tile 64x32, 2 CTAs/SM, double-buffered (R12 base).
// A: cp.async fp16 direct from g_h_f16 (gathered) / g_act_f16 into swizzled
//    smem; zero-fill for padding rows via src-size 0.
// B: fp32 weights from harness pointer (R6/R8 law). VECTORIZED path: each
//    thread owns one k-pair x 8 consecutive n -> 4 LDG.128 + 8 packs +
//    4 STS.128 per chunk (was 16 LDG.32 + 8 packs + 8 STS.32). B smem image
//    is byte-identical to R12.
// A smem: [m 128][k 32] fp16, 64B rows, XOR group swizzle
//   phys(m, kp) = m*64 + (((kp>>2) ^ ((m>>1)&3))<<4) + ((kp&3)<<2)
// B smem: [k2 16][n 128] fp16x2 slots, row stride 544B.
// ---------------------------------------------------------------------------
#define BK 32
#define ST_B   8192
#define B_ROWB 544
#define STAGE  16896          // 8192 + 16*544

template<bool G1>
__global__ void __launch_bounds__(256, 2) gemm_mma(
    const float* __restrict__ w,      // G1: w1 [E][C][H]; G2: w2 [E][H][C]
    const float* __restrict__ x,
    float* __restrict__ out)
{
    constexpr int K  = G1 ? C_DIM : H_DIM;   // reduction dim
    constexpr int NB = G1 ? H_DIM : C_DIM;   // output-feature dim
    constexpr int NC = K / BK;

    int e     = blockIdx.z;
    int pbase = g_poff[e];
    int pcnt  = g_poff[e + 1] - pbase;
    int row0  = blockIdx.y * 128;
    if (row0 >= pcnt) return;
    int coln0 = blockIdx.x * 128;
    int prow0 = pbase + row0;

    __shared__ __align__(16) char sm[2 * STAGE];
    uint32_t sb = smem_u32(sm);

    int tid = threadIdx.x, lane = tid & 31, wid = tid >> 5;
    int wm = wid & 1, wn = wid >> 1;
    int g4 = lane >> 2, t4 = lane & 3;

    int obase = g_offset[e];
    int cnt   = g_offset[e + 1] - obase;

    // ---- A cp.async sources: 2 rows per thread, one 16B chunk each ----
    int kq = tid & 3;                         // 16B chunk within 64B row-chunk
    const __half* asrc[2];
    uint32_t asz[2], adst[2];
#pragma unroll
    for (int p = 0; p < 2; p++) {
        int m = p * 64 + (tid >> 2);
        adst[p] = (uint32_t)(m * 64 + ((kq ^ ((m >> 1) & 3)) << 4));
        if (G1) {
            int gr = row0 + m;
            if (gr < cnt) {
                asrc[p] = g_h_f16 + (size_t)g_sorted[obase + gr] * C_DIM + kq * 8;
                asz[p] = 16;
            } else { asrc[p] = g_h_f16; asz[p] = 0; }
        } else {
            asrc[p] = g_act_f16 + (size_t)(prow0 + m) * H_DIM + kq * 8;
            asz[p] = 16;
        }
    }
    // ---- B source (vectorized): thread owns k-pair k2t x 8 consecutive n ----
    int k2t = tid >> 4;                       // 0..15  (k = 2*k2t, 2*k2t+1)
    int chp = tid & 15;                       // n block: n = 8*chp .. 8*chp+7
    const float* brow0 = w + (size_t)e * C_DIM * H_DIM + (size_t)(2 * k2t) * NB
                         + coln0 + chp * 8;   // row k
    uint32_t bsts = (uint32_t)(ST_B + k2t * B_ROWB + chp * 32);

    float acc[4][4][4];
#pragma unroll
    for (int i = 0; i < 4; i++)
#pragma unroll
        for (int j = 0; j < 4; j++)
#pragma unroll
            for (int q = 0; q < 4; q++) acc[i][j][q] = 0.f;

    float4 rb_k0a, rb_k0b, rb_k1a, rb_k1b;    // row k: n0..3, n4..7; row k+1: same

    auto cpa_chunk = [&](int c, uint32_t soff) {
#pragma unroll
        for (int p = 0; p < 2; p++)
            cp16s(sb + soff + adst[p], asrc[p] + c * BK, asz[p]);
        cp_commit();
    };
    auto stsb_chunk = [&](uint32_t soff) {
        uint4 v0, v1;
        v0.x = pack_f16(rb_k0a.x, rb_k1a.x);
        v0.y = pack_f16(rb_k0a.y, rb_k1a.y);
        v0.z = pack_f16(rb_k0a.z, rb_k1a.z);
        v0.w = pack_f16(rb_k0a.w, rb_k1a.w);
        v1.x = pack_f16(rb_k0b.x, rb_k1b.x);
        v1.y = pack_f16(rb_k0b.y, rb_k1b.y);
        v1.z = pack_f16(rb_k0b.z, rb_k1b.z);
        v1.w = pack_f16(rb_k0b.w, rb_k1b.w);
        *reinterpret_cast<uint4*>(sm + soff + bsts)      = v0;
        *reinterpret_cast<uint4*>(sm + soff + bsts + 16) = v1;
    };
    auto ldgb_chunk = [&](int c) {
        const float* p0 = brow0 + (size_t)c * BK * NB;       // row k
        const float* p1 = p0 + NB;                            // row k+1
        rb_k0a = *reinterpret_cast<const float4*>(p0);
        rb_k0b = *reinterpret_cast<const float4*>(p0 + 4);
        rb_k1a = *reinterpret_cast<const float4*>(p1);
        rb_k1b = *reinterpret_cast<const float4*>(p1 + 4);
    };

    // prologue: chunk0 (A async + B staged); B regs prefetch chunk1
    ldgb_chunk(0);
    cpa_chunk(0, 0);
    stsb_chunk(0);
    if (NC > 1) ldgb_chunk(1);
    cp_wait0();
    __syncthreads();

#pragma unroll 1
    for (int c = 0; c < NC; c++) {
        uint32_t st = sb + (uint32_t)(c & 1) * STAGE;

        // issue A copy for c+1 into the freed buffer (lands during compute)
        if (c + 1 < NC) cpa_chunk(c + 1, (uint32_t)((c + 1) & 1) * STAGE);

        // ---- compute chunk c ----
#pragma unroll
        for (int ks = 0; ks < 2; ks++) {
            uint32_t af[4][4];
#pragma unroll
            for (int mi = 0; mi < 4; mi++) {
                int m = wm * 64 + mi * 16 + g4;
                int s = (m >> 1) & 3;
                uint32_t r0 = st + (uint32_t)(m * 64 + (((ks * 2)     ^ s) << 4) + (t4 << 2));
                uint32_t r2 = st + (uint32_t)(m * 64 + (((ks * 2 + 1) ^ s) << 4) + (t4 << 2));
                af[mi][0] = lds32(r0);
                af[mi][1] = lds32(r0 + 512);   // row m+8, same swizzle key
                af[mi][2] = lds32(r2);
                af[mi][3] = lds32(r2 + 512);
            }
            uint32_t bf[4][2];
#pragma unroll
            for (int nt = 0; nt < 4; nt++) {
                uint32_t bb = st + ST_B
                    + (uint32_t)((ks * 8 + t4) * B_ROWB + (wn * 32 + nt * 8 + g4) * 4);
                bf[nt][0] = lds32(bb);
                bf[nt][1] = lds32(bb + 4 * B_ROWB);
            }
#pragma unroll
            for (int mi = 0; mi < 4; mi++)
#pragma unroll
                for (int nt = 0; nt < 4; nt++)
                    mma16816(acc[mi][nt], af[mi], bf[nt][0], bf[nt][1]);
        }

        // ---- stage B(c+1), prefetch B(c+2), wait for A(c+1), barrier ----
        if (c + 1 < NC) {
            stsb_chunk((uint32_t)((c + 1) & 1) * STAGE);
            if (c + 2 < NC) ldgb_chunk(c + 2);
            cp_wait0();
            __syncthreads();
        }
    }

    // ---- epilogue ----
    if (G1) {
#pragma unroll
        for (int mi = 0; mi < 4; mi++) {
            int gr = wm * 64 + mi * 16 + g4;
            size_t r0g = (size_t)(prow0 + gr)     * H_DIM;
            size_t r1g = (size_t)(prow0 + gr + 8) * H_DIM;
#pragma unroll
            for (int nt = 0; nt < 4; nt++) {
                int gc = coln0 + wn * 32 + nt * 8 + t4 * 2;
                float* cc = acc[mi][nt];
                float v0x = fmaxf(cc[0], 0.f); v0x *= v0x;
                float v0y = fmaxf(cc[1], 0.f); v0y *= v0y;
                float v1x = fmaxf(cc[2], 0.f); v1x *= v1x;
                float v1y = fmaxf(cc[3], 0.f); v1y *= v1y;
                *reinterpret_cast<uint32_t*>(g_act_f16 + r0g + gc) = pack_f16(v0x, v0y);
                *reinterpret_cast<uint32_t*>(g_act_f16 + r1g + gc) = pack_f16(v1x, v1y);
            }
        }
    } else {
#pragma unroll
        for (int mi = 0; mi < 4; mi++) {
            int rl0 = row0 + wm * 64 + mi * 16 + g4;
            int tok0 = -1, tok1 = -1;
            float sc0 = 0.f, sc1 = 0.f;
            if (rl0 < cnt)     { tok0 = g_sorted[obase + rl0];     sc0 = g_scale[tok0]; }
            if (rl0 + 8 < cnt) { tok1 = g_sorted[obase + rl0 + 8]; sc1 = g_scale[tok1]; }
#pragma unroll
            for (int nt = 0; nt < 4; nt++) {
                int gc = coln0 + wn * 32 + nt * 8 + t4 * 2;
                float* cc = acc[mi][nt];
                if (tok0 >= 0) {
                    size_t o = (size_t)tok0 * C_DIM + gc;
                    float2 xv = *reinterpret_cast<const float2*>(x + o);
                    float2 ov; ov.x = xv.x + cc[0] * sc0; ov.y = xv.y + cc[1] * sc0;
                    *reinterpret_cast<float2*>(out + o) = ov;
                }
                if (tok1 >= 0) {
                    size_t o = (size_t)tok1 * C_DIM + gc;
                    float2 xv = *reinterpret_cast<const float2*>(x + o);
                    float2 ov; ov.x = xv.x + cc[2] * sc1; ov.y = xv.y + cc[3] * sc1;
                    *reinterpret_cast<float2*>(out + o) = ov;
                }
            }
        }
    }
}

// ---------------------------------------------------------------------------
extern "C" void kernel_launch(void* const* d_in, const int* in_sizes, int n_in,
                              void* d_out, int out_size)
{
    const float* x       = (const float*)d_in[0];
    const int*   winners = (const int*)  d_in[1];
    const float* gamma   = (const float*)d_in[2];
    const float* beta    = (const float*)d_in[3];
    const float* w1      = (const float*)d_in[4];
    const float* w2      = (const float*)d_in[5];
    const float* wc      = (const float*)d_in[6];
    const float* bc      = (const float*)d_in[7];
    float* out = (float*)d_out;

    // zero per-expert counters via memset nodes (graph-capturable, no alloc)
    void* p_count = 0;
    void* p_cursor = 0;
    cudaGetSymbolAddress(&p_count,  g_count);
    cudaGetSymbolAddress(&p_cursor, g_cursor);
    cudaMemsetAsync(p_count,  0, E_NUM * sizeof(int));
    cudaMemsetAsync(p_cursor, 0, E_NUM * sizeof(int));

    ln_conf_kernel<<<N_TOK, 256>>>(x, winners, gamma, beta, wc, bc);
    scan_kernel<<<1, 32>>>();
    scatter_kernel<<<N_TOK / 256, 256>>>(winners);

    gemm_mma<true><<<dim3(H_DIM / 128, PADDED_CAP / 128, E_NUM), 256>>>(w1, x, out);
    gemm_mma<false><<<dim3(C_DIM / 128, PADDED_CAP / 128, E_NUM), 256>>>(w2, x, out);
}

// round 16
// speedup vs baseline: 1.1308x; 1.0406x over previous
#include <cuda_runtime.h>
#include <cuda_fp16.h>
#include <stdint.h>
#include <math.h>

#define N_TOK 8192
#define C_DIM 1024
#define H_DIM 4096
#define E_NUM 5
#define PADDED_CAP (N_TOK + E_NUM * 128)   // 8832

// ---------------------------------------------------------------------------
// Device scratch (allocation-free per harness rules)
// NOTE: activations in device globals are fine (R5-R15, incl. cp.async);
// staging WEIGHTS in device globals is a proven 8-11x regression (R6/R8) —
// weights are always read straight from the harness input pointers.
// ---------------------------------------------------------------------------
__device__ float g_scale[N_TOK];
__device__ int   g_sorted[N_TOK];
__device__ int   g_count[E_NUM];
__device__ int   g_offset[E_NUM + 1];
__device__ int   g_poff[E_NUM + 1];
__device__ int   g_cursor[E_NUM];

__device__ __align__(16) __half g_h_f16[(size_t)N_TOK * C_DIM];        // layernormed tokens
__device__ __align__(16) __half g_act_f16[(size_t)PADDED_CAP * H_DIM]; // relu^2 activations

// ---------------------------------------------------------------------------
// PTX helpers
// ---------------------------------------------------------------------------
__device__ __forceinline__ uint32_t smem_u32(const void* p) {
    uint32_t a;
    asm("{ .reg .u64 t; cvta.to.shared.u64 t, %1; cvt.u32.u64 %0, t; }" : "=r"(a) : "l"(p));
    return a;
}
__device__ __forceinline__ uint32_t lds32(uint32_t a) {
    uint32_t v;
    asm volatile("ld.shared.b32 %0, [%1];" : "=r"(v) : "r"(a));
    return v;
}
__device__ __forceinline__ void cp16s(uint32_t dst, const void* src, uint32_t sz) {
    asm volatile("cp.async.cg.shared.global [%0], [%1], 16, %2;" :: "r"(dst), "l"(src), "r"(sz));
}
__device__ __forceinline__ void cp_commit() {
    asm volatile("cp.async.commit_group;" ::: "memory");
}
__device__ __forceinline__ void cp_wait0() {
    asm volatile("cp.async.wait_group 0;" ::: "memory");
}
__device__ __forceinline__ void mma16816(float* c, const uint32_t* a, uint32_t b0, uint32_t b1) {
    asm volatile("mma.sync.aligned.m16n8k16.row.col.f32.f16.f16.f32 "
                 "{%0,%1,%2,%3}, {%4,%5,%6,%7}, {%8,%9}, {%0,%1,%2,%3};"
                 : "+f"(c[0]), "+f"(c[1]), "+f"(c[2]), "+f"(c[3])
                 : "r"(a[0]), "r"(a[1]), "r"(a[2]), "r"(a[3]), "r"(b0), "r"(b1));
}
__device__ __forceinline__ uint32_t pack_f16(float x, float y) {
    __half2 h = __floats2half2_rn(x, y);
    return *reinterpret_cast<uint32_t*>(&h);
}

// ---------------------------------------------------------------------------
// Small pipeline kernels (validated)
// ---------------------------------------------------------------------------
__global__ void __launch_bounds__(256) ln_conf_kernel(
    const float* __restrict__ x, const int* __restrict__ winners,
    const float* __restrict__ gamma, const float* __restrict__ beta,
    const float* __restrict__ wc, const float* __restrict__ bc)
{
    int n = blockIdx.x, tid = threadIdx.x;
    const float* xr = x + (size_t)n * C_DIM;
    float xv[4], s = 0.f, s2 = 0.f;
#pragma unroll
    for (int i = 0; i < 4; i++) { float v = xr[tid + 256 * i]; xv[i] = v; s += v; s2 += v * v; }
#pragma unroll
    for (int off = 16; off > 0; off >>= 1) {
        s  += __shfl_down_sync(0xffffffffu, s,  off);
        s2 += __shfl_down_sync(0xffffffffu, s2, off);
    }
    __shared__ float sh1[8], sh2[8];
    __shared__ float s_mean, s_rstd;
    int warp = tid >> 5, lane = tid & 31;
    if (lane == 0) { sh1[warp] = s; sh2[warp] = s2; }
    __syncthreads();
    if (tid == 0) {
        float ts = 0.f, ts2 = 0.f;
#pragma unroll
        for (int w = 0; w < 8; w++) { ts += sh1[w]; ts2 += sh2[w]; }
        float mean = ts * (1.f / C_DIM);
        float var = ts2 * (1.f / C_DIM) - mean * mean;
        s_mean = mean; s_rstd = rsqrtf(var + 1e-5f);
    }
    __syncthreads();
    float mean = s_mean, rstd = s_rstd;
    int win = winners[n];
    const float* wcr = wc + (size_t)win * C_DIM;
    float dot = 0.f;
#pragma unroll
    for (int i = 0; i < 4; i++) {
        int c = tid + 256 * i;
        float hv = (xv[i] - mean) * rstd * gamma[c] + beta[c];
        g_h_f16[(size_t)n * C_DIM + c] = __float2half_rn(hv);
        dot += hv * wcr[c];
    }
#pragma unroll
    for (int off = 16; off > 0; off >>= 1) dot += __shfl_down_sync(0xffffffffu, dot, off);
    if (lane == 0) sh1[warp] = dot;
    __syncthreads();
    if (tid == 0) {
        float t = 0.f;
#pragma unroll
        for (int w = 0; w < 8; w++) t += sh1[w];
        t += bc[win];
        float conf = 1.f / (1.f + expf(-t));
        g_scale[n] = conf / (conf + 1e-6f);
        atomicAdd(&g_count[win], 1);
    }
}

__global__ void scan_kernel() {
    if (threadIdx.x == 0) {
        int acc = 0, pacc = 0;
        g_offset[0] = 0; g_poff[0] = 0;
        for (int e = 0; e < E_NUM; e++) {
            int c = g_count[e];
            acc += c;
            g_offset[e + 1] = acc;
            g_cursor[e] = g_offset[e];
            pacc += ((c + 127) / 128) * 128;
            g_poff[e + 1] = pacc;
        }
    }
}

__global__ void scatter_kernel(const int* __restrict__ winners) {
    int n = blockIdx.x * blockDim.x + threadIdx.x;
    if (n < N_TOK) {
        int e = winners[n];
        int pos = atomicAdd(&g_cursor[e], 1);
        g_sorted[pos] = n;
    }
}

// ---------------------------------------------------------------------------
// HMMA GEMM, pure fp16 (1 MMA product per tile), CTA 128x128, BK=32,
// 8 warps (2M x 4N), warp tile 64x32, 2 CTAs/SM, double-buffered.
// A: cp.async fp16 direct from g_h_f16 (gathered) / g_act_f16 into swizzled
//    smem; zero-fill for padding rows via src-size 0.
// B: fp32 weights from harness pointer (R6/R8 law), coalesced column LDG,
//    register-staged, packed to fp16 in the inter-compute gap.
// A smem: [m 128][k 32] fp16, 64B rows, XOR group swizzle
//   phys(m, kp) = m*64 + (((kp>>2) ^ ((m>>1)&3))<<4) + ((kp&3)<<2)
// B smem: [k2 16][n 128] fp16x2 slots, row stride 544B.
// This is the measured champion configuration (R12, 542.9 us); R13-R15
// perturbations (staging hoist, fp32-B smem, vectorized B) all regressed.
// ---------------------------------------------------------------------------
#define BK 32
#define ST_B   8192
#define B_ROWB 544
#define STAGE  16896          // 8192 + 16*544

template<bool G1>
__global__ void __launch_bounds__(256, 2) gemm_mma(
    const float* __restrict__ w,      // G1: w1 [E][C][H]; G2: w2 [E][H][C]
    const float* __restrict__ x,
    float* __restrict__ out)
{
    constexpr int K  = G1 ? C_DIM : H_DIM;   // reduction dim
    constexpr int NB = G1 ? H_DIM : C_DIM;   // output-feature dim
    constexpr int NC = K / BK;

    int e     = blockIdx.z;
    int pbase = g_poff[e];
    int pcnt  = g_poff[e + 1] - pbase;
    int row0  = blockIdx.y * 128;
    if (row0 >= pcnt) return;
    int coln0 = blockIdx.x * 128;
    int prow0 = pbase + row0;

    __shared__ __align__(16) char sm[2 * STAGE];
    uint32_t sb = smem_u32(sm);

    int tid = threadIdx.x, lane = tid & 31, wid = tid >> 5;
    int wm = wid & 1, wn = wid >> 1;
    int g4 = lane >> 2, t4 = lane & 3;

    int obase = g_offset[e];
    int cnt   = g_offset[e + 1] - obase;

    // ---- A cp.async sources: 2 rows per thread, one 16B chunk each ----
    int kq = tid & 3;                         // 16B chunk within 64B row-chunk
    const __half* asrc[2];
    uint32_t asz[2], adst[2];
#pragma unroll
    for (int p = 0; p < 2; p++) {
        int m = p * 64 + (tid >> 2);
        adst[p] = (uint32_t)(m * 64 + ((kq ^ ((m >> 1) & 3)) << 4));
        if (G1) {
            int gr = row0 + m;
            if (gr < cnt) {
                asrc[p] = g_h_f16 + (size_t)g_sorted[obase + gr] * C_DIM + kq * 8;
                asz[p] = 16;
            } else { asrc[p] = g_h_f16; asz[p] = 0; }
        } else {
            asrc[p] = g_act_f16 + (size_t)(prow0 + m) * H_DIM + kq * 8;
            asz[p] = 16;
        }
    }
    // ---- B source: one n column per thread, 8 k-pairs ----
    int nb = tid & 127;
    int khalf = tid >> 7;                     // 0/1 -> k2 base 0 or 8
    const float* bcol = w + (size_t)e * C_DIM * H_DIM + (coln0 + nb);

    float acc[4][4][4];
#pragma unroll
    for (int i = 0; i < 4; i++)
#pragma unroll
        for (int j = 0; j < 4; j++)
#pragma unroll
            for (int q = 0; q < 4; q++) acc[i][j][q] = 0.f;

    float rb0[8], rb1[8];

    auto cpa_chunk = [&](int c, uint32_t soff) {
#pragma unroll
        for (int p = 0; p < 2; p++)
            cp16s(sb + soff + adst[p], asrc[p] + c * BK, asz[p]);
        cp_commit();
    };
    auto stsb_chunk = [&](uint32_t soff) {
#pragma unroll
        for (int p = 0; p < 8; p++) {
            int k2 = khalf * 8 + p;
            *reinterpret_cast<uint32_t*>(sm + soff + ST_B + k2 * B_ROWB + nb * 4)
                = pack_f16(rb0[p], rb1[p]);
        }
    };
    auto ldgb_chunk = [&](int c) {
        int k0 = c * BK;
#pragma unroll
        for (int p = 0; p < 8; p++) {
            int k = k0 + 2 * (khalf * 8 + p);
            rb0[p] = bcol[(size_t)k * NB];
            rb1[p] = bcol[(size_t)(k + 1) * NB];
        }
    };

    // prologue: chunk0 (A async + B staged); B regs prefetch chunk1
    ldgb_chunk(0);
    cpa_chunk(0, 0);
    stsb_chunk(0);
    if (NC > 1) ldgb_chunk(1);
    cp_wait0();
    __syncthreads();

#pragma unroll 1
    for (int c = 0; c < NC; c++) {
        uint32_t st = sb + (uint32_t)(c & 1) * STAGE;

        // issue A copy for c+1 into the freed buffer (lands during compute)
        if (c + 1 < NC) cpa_chunk(c + 1, (uint32_t)((c + 1) & 1) * STAGE);

        // ---- compute chunk c ----
#pragma unroll
        for (int ks = 0; ks < 2; ks++) {
            uint32_t af[4][4];
#pragma unroll
            for (int mi = 0; mi < 4; mi++) {
                int m = wm * 64 + mi * 16 + g4;
                int s = (m >> 1) & 3;
                uint32_t r0 = st + (uint32_t)(m * 64 + (((ks * 2)     ^ s) << 4) + (t4 << 2));
                uint32_t r2 = st + (uint32_t)(m * 64 + (((ks * 2 + 1) ^ s) << 4) + (t4 << 2));
                af[mi][0] = lds32(r0);
                af[mi][1] = lds32(r0 + 512);   // row m+8, same swizzle key
                af[mi][2] = lds32(r2);
                af[mi][3] = lds32(r2 + 512);
            }
            uint32_t bf[4][2];
#pragma unroll
            for (int nt = 0; nt < 4; nt++) {
                uint32_t bb = st + ST_B
                    + (uint32_t)((ks * 8 + t4) * B_ROWB + (wn * 32 + nt * 8 + g4) * 4);
                bf[nt][0] = lds32(bb);
                bf[nt][1] = lds32(bb + 4 * B_ROWB);
            }
#pragma unroll
            for (int mi = 0; mi < 4; mi++)
#pragma unroll
                for (int nt = 0; nt < 4; nt++)
                    mma16816(acc[mi][nt], af[mi], bf[nt][0], bf[nt][1]);
        }

        // ---- stage B(c+1), prefetch B(c+2), wait for A(c+1), barrier ----
        if (c + 1 < NC) {
            stsb_chunk((uint32_t)((c + 1) & 1) * STAGE);
            if (c + 2 < NC) ldgb_chunk(c + 2);
            cp_wait0();
            __syncthreads();
        }
    }

    // ---- epilogue ----
    if (G1) {
#pragma unroll
        for (int mi = 0; mi < 4; mi++) {
            int gr = wm * 64 + mi * 16 + g4;
            size_t r0g = (size_t)(prow0 + gr)     * H_DIM;
            size_t r1g = (size_t)(prow0 + gr + 8) * H_DIM;
#pragma unroll
            for (int nt = 0; nt < 4; nt++) {
                int gc = coln0 + wn * 32 + nt * 8 + t4 * 2;
                float* cc = acc[mi][nt];
                float v0x = fmaxf(cc[0], 0.f); v0x *= v0x;
                float v0y = fmaxf(cc[1], 0.f); v0y *= v0y;
                float v1x = fmaxf(cc[2], 0.f); v1x *= v1x;
                float v1y = fmaxf(cc[3], 0.f); v1y *= v1y;
                *reinterpret_cast<uint32_t*>(g_act_f16 + r0g + gc) = pack_f16(v0x, v0y);
                *reinterpret_cast<uint32_t*>(g_act_f16 + r1g + gc) = pack_f16(v1x, v1y);
            }
        }
    } else {
#pragma unroll
        for (int mi = 0; mi < 4; mi++) {
            int rl0 = row0 + wm * 64 + mi * 16 + g4;
            int tok0 = -1, tok1 = -1;
            float sc0 = 0.f, sc1 = 0.f;
            if (rl0 < cnt)     { tok0 = g_sorted[obase + rl0];     sc0 = g_scale[tok0]; }
            if (rl0 + 8 < cnt) { tok1 = g_sorted[obase + rl0 + 8]; sc1 = g_scale[tok1]; }
#pragma unroll
            for (int nt = 0; nt < 4; nt++) {
                int gc = coln0 + wn * 32 + nt * 8 + t4 * 2;
                float* cc = acc[mi][nt];
                if (tok0 >= 0) {
                    size_t o = (size_t)tok0 * C_DIM + gc;
                    float2 xv = *reinterpret_cast<const float2*>(x + o);
                    float2 ov; ov.x = xv.x + cc[0] * sc0; ov.y = xv.y + cc[1] * sc0;
                    *reinterpret_cast<float2*>(out + o) = ov;
                }
                if (tok1 >= 0) {
                    size_t o = (size_t)tok1 * C_DIM + gc;
                    float2 xv = *reinterpret_cast<const float2*>(x + o);
                    float2 ov; ov.x = xv.x + cc[2] * sc1; ov.y = xv.y + cc[3] * sc1;
                    *reinterpret_cast<float2*>(out + o) = ov;
                }
            }
        }
    }
}

// ---------------------------------------------------------------------------
extern "C" void kernel_launch(void* const* d_in, const int* in_sizes, int n_in,
                              void* d_out, int out_size)
{
    const float* x       = (const float*)d_in[0];
    const int*   winners = (const int*)  d_in[1];
    const float* gamma   = (const float*)d_in[2];
    const float* beta    = (const float*)d_in[3];
    const float* w1      = (const float*)d_in[4];
    const float* w2      = (const float*)d_in[5];
    const float* wc      = (const float*)d_in[6];
    const float* bc      = (const float*)d_in[7];
    float* out = (float*)d_out;

    // zero per-expert counters via memset nodes (graph-capturable, no alloc)
    void* p_count = 0;
    void* p_cursor = 0;
    cudaGetSymbolAddress(&p_count,  g_count);
    cudaGetSymbolAddress(&p_cursor, g_cursor);
    cudaMemsetAsync(p_count,  0, E_NUM * sizeof(int));
    cudaMemsetAsync(p_cursor, 0, E_NUM * sizeof(int));

    ln_conf_kernel<<<N_TOK, 256>>>(x, winners, gamma, beta, wc, bc);
    scan_kernel<<<1, 32>>>();
    scatter_kernel<<<N_TOK / 256, 256>>>(winners);

    gemm_mma<true><<<dim3(H_DIM / 128, PADDED_CAP / 128, E_NUM), 256>>>(w1, x, out);
    gemm_mma<false><<<dim3(C_DIM / 128, PADDED_CAP / 128, E_NUM), 256>>>(w2, x, out);
}

// round 17
// speedup vs baseline: 1.1330x; 1.0019x over previous
#include <cuda_runtime.h>
#include <cuda_fp16.h>
#include <stdint.h>
#include <math.h>

#define N_TOK 8192
#define C_DIM 1024
#define H_DIM 4096
#define E_NUM 5
#define PADDED_CAP (N_TOK + E_NUM * 128)   // 8832

// ---------------------------------------------------------------------------
// Device scratch (allocation-free per harness rules)
// NOTE: activations in device globals are fine (R5-R16, incl. cp.async);
// staging WEIGHTS in device globals is a proven 8-11x regression (R6/R8) —
// weights are always read straight from the harness input pointers.
// ---------------------------------------------------------------------------
__device__ float g_scale[N_TOK];
__device__ int   g_sorted[N_TOK];
__device__ int   g_count[E_NUM];
__device__ int   g_offset[E_NUM + 1];
__device__ int   g_poff[E_NUM + 1];
__device__ int   g_cursor[E_NUM];

__device__ __align__(16) __half g_h_f16[(size_t)N_TOK * C_DIM];        // layernormed tokens
__device__ __align__(16) __half g_act_f16[(size_t)PADDED_CAP * H_DIM]; // relu^2 activations

// ---------------------------------------------------------------------------
// PTX helpers
// ---------------------------------------------------------------------------
__device__ __forceinline__ uint32_t smem_u32(const void* p) {
    uint32_t a;
    asm("{ .reg .u64 t; cvta.to.shared.u64 t, %1; cvt.u32.u64 %0, t; }" : "=r"(a) : "l"(p));
    return a;
}
__device__ __forceinline__ uint32_t lds32(uint32_t a) {
    uint32_t v;
    asm volatile("ld.shared.b32 %0, [%1];" : "=r"(v) : "r"(a));
    return v;
}
__device__ __forceinline__ void cp16s(uint32_t dst, const void* src, uint32_t sz) {
    asm volatile("cp.async.cg.shared.global [%0], [%1], 16, %2;" :: "r"(dst), "l"(src), "r"(sz));
}
__device__ __forceinline__ void cp_commit() {
    asm volatile("cp.async.commit_group;" ::: "memory");
}
__device__ __forceinline__ void cp_wait0() {
    asm volatile("cp.async.wait_group 0;" ::: "memory");
}
__device__ __forceinline__ void mma16816(float* c, const uint32_t* a, uint32_t b0, uint32_t b1) {
    asm volatile("mma.sync.aligned.m16n8k16.row.col.f32.f16.f16.f32 "
                 "{%0,%1,%2,%3}, {%4,%5,%6,%7}, {%8,%9}, {%0,%1,%2,%3};"
                 : "+f"(c[0]), "+f"(c[1]), "+f"(c[2]), "+f"(c[3])
                 : "r"(a[0]), "r"(a[1]), "r"(a[2]), "r"(a[3]), "r"(b0), "r"(b1));
}
__device__ __forceinline__ uint32_t pack_f16(float x, float y) {
    __half2 h = __floats2half2_rn(x, y);
    return *reinterpret_cast<uint32_t*>(&h);
}

// ---------------------------------------------------------------------------
// Small pipeline kernels (validated)
// ---------------------------------------------------------------------------
__global__ void __launch_bounds__(256) ln_conf_kernel(
    const float* __restrict__ x, const int* __restrict__ winners,
    const float* __restrict__ gamma, const float* __restrict__ beta,
    const float* __restrict__ wc, const float* __restrict__ bc)
{
    int n = blockIdx.x, tid = threadIdx.x;
    const float* xr = x + (size_t)n * C_DIM;
    float xv[4], s = 0.f, s2 = 0.f;
#pragma unroll
    for (int i = 0; i < 4; i++) { float v = xr[tid + 256 * i]; xv[i] = v; s += v; s2 += v * v; }
#pragma unroll
    for (int off = 16; off > 0; off >>= 1) {
        s  += __shfl_down_sync(0xffffffffu, s,  off);
        s2 += __shfl_down_sync(0xffffffffu, s2, off);
    }
    __shared__ float sh1[8], sh2[8];
    __shared__ float s_mean, s_rstd;
    int warp = tid >> 5, lane = tid & 31;
    if (lane == 0) { sh1[warp] = s; sh2[warp] = s2; }
    __syncthreads();
    if (tid == 0) {
        float ts = 0.f, ts2 = 0.f;
#pragma unroll
        for (int w = 0; w < 8; w++) { ts += sh1[w]; ts2 += sh2[w]; }
        float mean = ts * (1.f / C_DIM);
        float var = ts2 * (1.f / C_DIM) - mean * mean;
        s_mean = mean; s_rstd = rsqrtf(var + 1e-5f);
    }
    __syncthreads();
    float mean = s_mean, rstd = s_rstd;
    int win = winners[n];
    const float* wcr = wc + (size_t)win * C_DIM;
    float dot = 0.f;
#pragma unroll
    for (int i = 0; i < 4; i++) {
        int c = tid + 256 * i;
        float hv = (xv[i] - mean) * rstd * gamma[c] + beta[c];
        g_h_f16[(size_t)n * C_DIM + c] = __float2half_rn(hv);
        dot += hv * wcr[c];
    }
#pragma unroll
    for (int off = 16; off > 0; off >>= 1) dot += __shfl_down_sync(0xffffffffu, dot, off);
    if (lane == 0) sh1[warp] = dot;
    __syncthreads();
    if (tid == 0) {
        float t = 0.f;
#pragma unroll
        for (int w = 0; w < 8; w++) t += sh1[w];
        t += bc[win];
        float conf = 1.f / (1.f + expf(-t));
        g_scale[n] = conf / (conf + 1e-6f);
        atomicAdd(&g_count[win], 1);
    }
}

__global__ void scan_kernel() {
    if (threadIdx.x == 0) {
        int acc = 0, pacc = 0;
        g_offset[0] = 0; g_poff[0] = 0;
        for (int e = 0; e < E_NUM; e++) {
            int c = g_count[e];
            acc += c;
            g_offset[e + 1] = acc;
            g_cursor[e] = g_offset[e];
            pacc += ((c + 127) / 128) * 128;
            g_poff[e + 1] = pacc;
        }
    }
}

__global__ void scatter_kernel(const int* __restrict__ winners) {
    int n = blockIdx.x * blockDim.x + threadIdx.x;
    if (n < N_TOK) {
        int e = winners[n];
        int pos = atomicAdd(&g_cursor[e], 1);
        g_sorted[pos] = n;
    }
}

// ---------------------------------------------------------------------------
// HMMA GEMM, pure fp16 (1 MMA product per tile), CTA 128x128, BK=32,
// 8 warps (2M x 4N), warp tile 64x32, 2 CTAs/SM, double-buffered.
// A: cp.async fp16 direct from g_h_f16 (gathered) / g_act_f16 into swizzled
//    smem; zero-fill for padding rows via src-size 0.
// B: fp32 weights from harness pointer (R6/R8 law), coalesced column LDG,
//    register-staged, packed to fp16 in the inter-compute gap.
// A smem: [m 128][k 32] fp16, 64B rows, XOR group swizzle
//   phys(m, kp) = m*64 + (((kp>>2) ^ ((m>>1)&3))<<4) + ((kp&3)<<2)
// B smem: [k2 16][n 128] fp16x2 slots, row stride 544B.
// Champion configuration (R12; 542.9/545.2 us across two runs). All local
// perturbations measured and regressed: staging hoist (R13 +3%), fp32-B smem
// (R14 +14%), vectorized B (R15 +4%); scheduling levers neutral (R7/R9/R10).
// ---------------------------------------------------------------------------
#define BK 32
#define ST_B   8192
#define B_ROWB 544
#define STAGE  16896          // 8192 + 16*544

template<bool G1>
__global__ void __launch_bounds__(256, 2) gemm_mma(
    const float* __restrict__ w,      // G1: w1 [E][C][H]; G2: w2 [E][H][C]
    const float* __restrict__ x,
    float* __restrict__ out)
{
    constexpr int K  = G1 ? C_DIM : H_DIM;   // reduction dim
    constexpr int NB = G1 ? H_DIM : C_DIM;   // output-feature dim
    constexpr int NC = K / BK;

    int e     = blockIdx.z;
    int pbase = g_poff[e];
    int pcnt  = g_poff[e + 1] - pbase;
    int row0  = blockIdx.y * 128;
    if (row0 >= pcnt) return;
    int coln0 = blockIdx.x * 128;
    int prow0 = pbase + row0;

    __shared__ __align__(16) char sm[2 * STAGE];
    uint32_t sb = smem_u32(sm);

    int tid = threadIdx.x, lane = tid & 31, wid = tid >> 5;
    int wm = wid & 1, wn = wid >> 1;
    int g4 = lane >> 2, t4 = lane & 3;

    int obase = g_offset[e];
    int cnt   = g_offset[e + 1] - obase;

    // ---- A cp.async sources: 2 rows per thread, one 16B chunk each ----
    int kq = tid & 3;                         // 16B chunk within 64B row-chunk
    const __half* asrc[2];
    uint32_t asz[2], adst[2];
#pragma unroll
    for (int p = 0; p < 2; p++) {
        int m = p * 64 + (tid >> 2);
        adst[p] = (uint32_t)(m * 64 + ((kq ^ ((m >> 1) & 3)) << 4));
        if (G1) {
            int gr = row0 + m;
            if (gr < cnt) {
                asrc[p] = g_h_f16 + (size_t)g_sorted[obase + gr] * C_DIM + kq * 8;
                asz[p] = 16;
            } else { asrc[p] = g_h_f16; asz[p] = 0; }
        } else {
            asrc[p] = g_act_f16 + (size_t)(prow0 + m) * H_DIM + kq * 8;
            asz[p] = 16;
        }
    }
    // ---- B source: one n column per thread, 8 k-pairs ----
    int nb = tid & 127;
    int khalf = tid >> 7;                     // 0/1 -> k2 base 0 or 8
    const float* bcol = w + (size_t)e * C_DIM * H_DIM + (coln0 + nb);

    float acc[4][4][4];
#pragma unroll
    for (int i = 0; i < 4; i++)
#pragma unroll
        for (int j = 0; j < 4; j++)
#pragma unroll
            for (int q = 0; q < 4; q++) acc[i][j][q] = 0.f;

    float rb0[8], rb1[8];

    auto cpa_chunk = [&](int c, uint32_t soff) {
#pragma unroll
        for (int p = 0; p < 2; p++)
            cp16s(sb + soff + adst[p], asrc[p] + c * BK, asz[p]);
        cp_commit();
    };
    auto stsb_chunk = [&](uint32_t soff) {
#pragma unroll
        for (int p = 0; p < 8; p++) {
            int k2 = khalf * 8 + p;
            *reinterpret_cast<uint32_t*>(sm + soff + ST_B + k2 * B_ROWB + nb * 4)
                = pack_f16(rb0[p], rb1[p]);
        }
    };
    auto ldgb_chunk = [&](int c) {
        int k0 = c * BK;
#pragma unroll
        for (int p = 0; p < 8; p++) {
            int k = k0 + 2 * (khalf * 8 + p);
            rb0[p] = bcol[(size_t)k * NB];
            rb1[p] = bcol[(size_t)(k + 1) * NB];
        }
    };

    // prologue: chunk0 (A async + B staged); B regs prefetch chunk1
    ldgb_chunk(0);
    cpa_chunk(0, 0);
    stsb_chunk(0);
    if (NC > 1) ldgb_chunk(1);
    cp_wait0();
    __syncthreads();

#pragma unroll 1
    for (int c = 0; c < NC; c++) {
        uint32_t st = sb + (uint32_t)(c & 1) * STAGE;

        // issue A copy for c+1 into the freed buffer (lands during compute)
        if (c + 1 < NC) cpa_chunk(c + 1, (uint32_t)((c + 1) & 1) * STAGE);

        // ---- compute chunk c ----
#pragma unroll
        for (int ks = 0; ks < 2; ks++) {
            uint32_t af[4][4];
#pragma unroll
            for (int mi = 0; mi < 4; mi++) {
                int m = wm * 64 + mi * 16 + g4;
                int s = (m >> 1) & 3;
                uint32_t r0 = st + (uint32_t)(m * 64 + (((ks * 2)     ^ s) << 4) + (t4 << 2));
                uint32_t r2 = st + (uint32_t)(m * 64 + (((ks * 2 + 1) ^ s) << 4) + (t4 << 2));
                af[mi][0] = lds32(r0);
                af[mi][1] = lds32(r0 + 512);   // row m+8, same swizzle key
                af[mi][2] = lds32(r2);
                af[mi][3] = lds32(r2 + 512);
            }
            uint32_t bf[4][2];
#pragma unroll
            for (int nt = 0; nt < 4; nt++) {
                uint32_t bb = st + ST_B
                    + (uint32_t)((ks * 8 + t4) * B_ROWB + (wn * 32 + nt * 8 + g4) * 4);
                bf[nt][0] = lds32(bb);
                bf[nt][1] = lds32(bb + 4 * B_ROWB);
            }
#pragma unroll
            for (int mi = 0; mi < 4; mi++)
#pragma unroll
                for (int nt = 0; nt < 4; nt++)
                    mma16816(acc[mi][nt], af[mi], bf[nt][0], bf[nt][1]);
        }

        // ---- stage B(c+1), prefetch B(c+2), wait for A(c+1), barrier ----
        if (c + 1 < NC) {
            stsb_chunk((uint32_t)((c + 1) & 1) * STAGE);
            if (c + 2 < NC) ldgb_chunk(c + 2);
            cp_wait0();
            __syncthreads();
        }
    }

    // ---- epilogue ----
    if (G1) {
#pragma unroll
        for (int mi = 0; mi < 4; mi++) {
            int gr = wm * 64 + mi * 16 + g4;
            size_t r0g = (size_t)(prow0 + gr)     * H_DIM;
            size_t r1g = (size_t)(prow0 + gr + 8) * H_DIM;
#pragma unroll
            for (int nt = 0; nt < 4; nt++) {
                int gc = coln0 + wn * 32 + nt * 8 + t4 * 2;
                float* cc = acc[mi][nt];
                float v0x = fmaxf(cc[0], 0.f); v0x *= v0x;
                float v0y = fmaxf(cc[1], 0.f); v0y *= v0y;
                float v1x = fmaxf(cc[2], 0.f); v1x *= v1x;
                float v1y = fmaxf(cc[3], 0.f); v1y *= v1y;
                *reinterpret_cast<uint32_t*>(g_act_f16 + r0g + gc) = pack_f16(v0x, v0y);
                *reinterpret_cast<uint32_t*>(g_act_f16 + r1g + gc) = pack_f16(v1x, v1y);
            }
        }
    } else {
#pragma unroll
        for (int mi = 0; mi < 4; mi++) {
            int rl0 = row0 + wm * 64 + mi * 16 + g4;
            int tok0 = -1, tok1 = -1;
            float sc0 = 0.f, sc1 = 0.f;
            if (rl0 < cnt)     { tok0 = g_sorted[obase + rl0];     sc0 = g_scale[tok0]; }
            if (rl0 + 8 < cnt) { tok1 = g_sorted[obase + rl0 + 8]; sc1 = g_scale[tok1]; }
#pragma unroll
            for (int nt = 0; nt < 4; nt++) {
                int gc = coln0 + wn * 32 + nt * 8 + t4 * 2;
                float* cc = acc[mi][nt];
                if (tok0 >= 0) {
                    size_t o = (size_t)tok0 * C_DIM + gc;
                    float2 xv = *reinterpret_cast<const float2*>(x + o);
                    float2 ov; ov.x = xv.x + cc[0] * sc0; ov.y = xv.y + cc[1] * sc0;
                    *reinterpret_cast<float2*>(out + o) = ov;
                }
                if (tok1 >= 0) {
                    size_t o = (size_t)tok1 * C_DIM + gc;
                    float2 xv = *reinterpret_cast<const float2*>(x + o);
                    float2 ov; ov.x = xv.x + cc[2] * sc1; ov.y = xv.y + cc[3] * sc1;
                    *reinterpret_cast<float2*>(out + o) = ov;
                }
            }
        }
    }
}

// ---------------------------------------------------------------------------
extern "C" void kernel_launch(void* const* d_in, const int* in_sizes, int n_in,
                              void* d_out, int out_size)
{
    const float* x       = (const float*)d_in[0];
    const int*   winners = (const int*)  d_in[1];
    const float* gamma   = (const float*)d_in[2];
    const float* beta    = (const float*)d_in[3];
    const float* w1      = (const float*)d_in[4];
    const float* w2      = (const float*)d_in[5];
    const float* wc      = (const float*)d_in[6];
    const float* bc      = (const float*)d_in[7];
    float* out = (float*)d_out;

    // zero per-expert counters via memset nodes (graph-capturable, no alloc)
    void* p_count = 0;
    void* p_cursor = 0;
    cudaGetSymbolAddress(&p_count,  g_count);
    cudaGetSymbolAddress(&p_cursor, g_cursor);
    cudaMemsetAsync(p_count,  0, E_NUM * sizeof(int));
    cudaMemsetAsync(p_cursor, 0, E_NUM * sizeof(int));

    ln_conf_kernel<<<N_TOK, 256>>>(x, winners, gamma, beta, wc, bc);
    scan_kernel<<<1, 32>>>();
    scatter_kernel<<<N_TOK / 256, 256>>>(winners);

    gemm_mma<true><<<dim3(H_DIM / 128, PADDED_CAP / 128, E_NUM), 256>>>(w1, x, out);
    gemm_mma<false><<<dim3(C_DIM / 128, PADDED_CAP / 128, E_NUM), 256>>>(w2, x, out);
}